// round 1
// baseline (speedup 1.0000x reference)
#include <cuda_runtime.h>
#include <math.h>

// Problem shape (LongcatFlashTopkRouter): T=16384, D=4096, E=256
#define TOP_K 8
#define ROUTED_SCALE 1.5f

// ---------------- GEMM: C[t,e] = dot(H[t,:], W[e,:])  (NT, fp32) -------------
#define BM 128
#define BN 128
#define BK 32
#define TM 8
#define TN 8
// 256 threads: 16x16 grid of 8x8 micro-tiles

__global__ __launch_bounds__(256, 2)
void sgemm_nt_kernel(const float* __restrict__ A,   // [T, D] row-major
                     const float* __restrict__ B,   // [E, D] row-major
                     float* __restrict__ C,         // [T, E] row-major
                     int T, int D, int E) {
    __shared__ float As[BK][BM];  // transposed tiles: As[k][m]
    __shared__ float Bs[BK][BN];  // Bs[k][n]

    const int tid = threadIdx.x;
    const int tx  = tid % 16;          // micro-tile col group
    const int ty  = tid / 16;          // micro-tile row group

    const int blockRow = blockIdx.y * BM;
    const int blockCol = blockIdx.x * BN;

    const float* Ab = A + (size_t)blockRow * D;
    const float* Bb = B + (size_t)blockCol * D;

    float acc[TM][TN];
    #pragma unroll
    for (int i = 0; i < TM; i++)
        #pragma unroll
        for (int j = 0; j < TN; j++) acc[i][j] = 0.0f;

    // global-load mapping: 128 rows x 8 float4 columns, 4 rows-groups per thread
    const int lr = tid / 8;    // 0..31
    const int lc = tid % 8;    // 0..7  (float4 column within BK)

    for (int kt = 0; kt < D; kt += BK) {
        #pragma unroll
        for (int i = 0; i < 4; i++) {
            const int row = lr + i * 32;
            float4 va = *(const float4*)(Ab + (size_t)row * D + kt + lc * 4);
            As[lc * 4 + 0][row] = va.x;
            As[lc * 4 + 1][row] = va.y;
            As[lc * 4 + 2][row] = va.z;
            As[lc * 4 + 3][row] = va.w;
            float4 vb = *(const float4*)(Bb + (size_t)row * D + kt + lc * 4);
            Bs[lc * 4 + 0][row] = vb.x;
            Bs[lc * 4 + 1][row] = vb.y;
            Bs[lc * 4 + 2][row] = vb.z;
            Bs[lc * 4 + 3][row] = vb.w;
        }
        __syncthreads();

        #pragma unroll
        for (int k = 0; k < BK; k++) {
            float a[TM], b[TN];
            *(float4*)&a[0] = *(const float4*)&As[k][ty * TM];
            *(float4*)&a[4] = *(const float4*)&As[k][ty * TM + 4];
            *(float4*)&b[0] = *(const float4*)&Bs[k][tx * TN];
            *(float4*)&b[4] = *(const float4*)&Bs[k][tx * TN + 4];
            #pragma unroll
            for (int i = 0; i < TM; i++)
                #pragma unroll
                for (int j = 0; j < TN; j++)
                    acc[i][j] = fmaf(a[i], b[j], acc[i][j]);
        }
        __syncthreads();
    }

    // epilogue: vectorized stores
    #pragma unroll
    for (int i = 0; i < TM; i++) {
        const int row = blockRow + ty * TM + i;
        float* Cr = C + (size_t)row * E + blockCol + tx * TN;
        float4 v0 = make_float4(acc[i][0], acc[i][1], acc[i][2], acc[i][3]);
        float4 v1 = make_float4(acc[i][4], acc[i][5], acc[i][6], acc[i][7]);
        *(float4*)(Cr + 0) = v0;
        *(float4*)(Cr + 4) = v1;
    }
}

// ------------- Routing: softmax -> biased top-k -> gather unbiased -----------
// One CTA of 256 threads per token (E = 256, one expert per thread).
__global__ __launch_bounds__(256)
void router_topk_kernel(const float* __restrict__ C,     // [T, E]
                        const float* __restrict__ bias,  // [E]
                        float* __restrict__ wout,        // [T, TOP_K]
                        float* __restrict__ iout,        // [T, TOP_K] (values)
                        int T, int E) {
    const int t    = blockIdx.x;
    const int e    = threadIdx.x;
    const int lane = e & 31;
    const int warp = e >> 5;

    __shared__ float red[8];
    __shared__ float bval[8];
    __shared__ int   bidx[8];
    __shared__ int   sel;

    float s = C[(size_t)t * E + e];

    // --- max reduce ---
    float m = s;
    #pragma unroll
    for (int off = 16; off > 0; off >>= 1)
        m = fmaxf(m, __shfl_xor_sync(0xffffffffu, m, off));
    if (lane == 0) red[warp] = m;
    __syncthreads();
    if (warp == 0) {
        float v = red[lane & 7];
        #pragma unroll
        for (int off = 4; off > 0; off >>= 1)
            v = fmaxf(v, __shfl_xor_sync(0xffffffffu, v, off));
        if (lane == 0) red[0] = v;
    }
    __syncthreads();
    const float gmax = red[0];
    __syncthreads();

    // --- sum reduce ---
    float p = __expf(s - gmax);
    float su = p;
    #pragma unroll
    for (int off = 16; off > 0; off >>= 1)
        su += __shfl_xor_sync(0xffffffffu, su, off);
    if (lane == 0) red[warp] = su;
    __syncthreads();
    if (warp == 0) {
        float v = red[lane & 7];
        #pragma unroll
        for (int off = 4; off > 0; off >>= 1)
            v += __shfl_xor_sync(0xffffffffu, v, off);
        if (lane == 0) red[0] = v;
    }
    __syncthreads();
    const float inv_sum = 1.0f / red[0];

    const float prob   = p * inv_sum;         // unbiased softmax score
    float       choice = prob + bias[e];      // biased score for selection

    // --- top-8 by repeated argmax (tie -> lowest index, matches lax.top_k) ---
    for (int k = 0; k < TOP_K; k++) {
        float v  = choice;
        int   id = e;
        #pragma unroll
        for (int off = 16; off > 0; off >>= 1) {
            float ov = __shfl_xor_sync(0xffffffffu, v, off);
            int   oi = __shfl_xor_sync(0xffffffffu, id, off);
            if (ov > v || (ov == v && oi < id)) { v = ov; id = oi; }
        }
        if (lane == 0) { bval[warp] = v; bidx[warp] = id; }
        __syncthreads();
        if (e == 0) {
            float bv = bval[0]; int bi = bidx[0];
            #pragma unroll
            for (int w = 1; w < 8; w++) {
                if (bval[w] > bv || (bval[w] == bv && bidx[w] < bi)) {
                    bv = bval[w]; bi = bidx[w];
                }
            }
            sel = bi;
        }
        __syncthreads();
        const int bi = sel;
        if (e == bi) {
            wout[(size_t)t * TOP_K + k] = prob * ROUTED_SCALE;
            iout[(size_t)t * TOP_K + k] = (float)bi;
            choice = -INFINITY;
        }
        __syncthreads();
    }
}

// ----------------------------- launch ---------------------------------------
extern "C" void kernel_launch(void* const* d_in, const int* in_sizes, int n_in,
                              void* d_out, int out_size) {
    const float* H    = (const float*)d_in[0];  // [T, D]
    const float* W    = (const float*)d_in[1];  // [E, D]
    const float* bias = (const float*)d_in[2];  // [E]

    const int E = in_sizes[2];                  // 256
    const int D = in_sizes[1] / E;              // 4096
    const int T = in_sizes[0] / D;              // 16384

    float* out   = (float*)d_out;
    float* C     = out;                              // [T, E]
    float* wout  = out + (size_t)T * E;              // [T, TOP_K]
    float* iout  = wout + (size_t)T * TOP_K;         // [T, TOP_K]

    dim3 grid(E / BN, T / BM);
    sgemm_nt_kernel<<<grid, 256>>>(H, W, C, T, D, E);
    router_topk_kernel<<<T, 256>>>(C, bias, wout, iout, T, E);
}

// round 3
// speedup vs baseline: 4.5780x; 4.5780x over previous
#include <cuda_runtime.h>
#include <math.h>
#include <stdint.h>

// LongcatFlashTopkRouter: T=16384, D=4096, E=256
#define TOP_K 8
#define ROUTED_SCALE 1.5f

// tcgen05 is arch-specific: only available when compiling for sm_103a/sm_100a
// (feature macros below), NOT for plain sm_103/compute_103 passes.
#if defined(__CUDA_ARCH__) && \
    (defined(__CUDA_ARCH_FEAT_SM103_ALL) || defined(__CUDA_ARCH_FEAT_SM100_ALL) || \
     defined(__CUDA_ARCH_FEAT_SM101_ALL))
#define HAS_TC 1
#else
#define HAS_TC 0
#endif

// ---------------------------------------------------------------------------
// GEMM: C[t,e] = dot(H[t,:], W[e,:])   (NT, fp32 accuracy)
// Tile: BM=128 x BN=128 x BK=32 floats
// ---------------------------------------------------------------------------
#define BM 128
#define BN 128
#define BKF 32
#define STAGE_BYTES 65536
#define A_HI_OFF 0
#define A_LO_OFF 16384
#define B_HI_OFF 32768
#define B_LO_OFF 49152
#define DYN_SMEM (2 * STAGE_BYTES + 2048)

// idesc: dtype=F32(1)<<4 | atype=TF32(2)<<7 | btype=TF32(2)<<10 | (N/8)<<17 | (M/16)<<24
#define IDESC 0x8200910u
#define TMEM_NCOLS 128

#if HAS_TC
__device__ __forceinline__ uint32_t smem_u32(const void* p) {
    uint32_t a;
    asm("{ .reg .u64 t; cvta.to.shared.u64 t, %1; cvt.u32.u64 %0, t; }" : "=r"(a) : "l"(p));
    return a;
}

__device__ __forceinline__ float f2tf32(float x) {
    uint32_t u;
    asm("cvt.rna.tf32.f32 %0, %1;" : "=r"(u) : "f"(x));
    return __uint_as_float(u);
}

#define SWZ128(o) ((o) ^ (((o) >> 3) & 0x70))

// 64-bit SMEM descriptor: SW128, Blackwell, LBO=1, SBO=64
__device__ __forceinline__ uint64_t mk_desc(uint32_t addr) {
    const uint64_t base =
        (uint64_t(2)  << 61) | (uint64_t(1) << 46) | (uint64_t(64) << 32) | (uint64_t(1) << 16);
    return base | ((uint64_t)(addr >> 4) & 0x3FFF);
}

__device__ __forceinline__ void mma_tf32_ss(uint32_t d_tmem, uint64_t a_desc, uint64_t b_desc,
                                            uint32_t idesc, uint32_t en) {
    uint32_t z = 0;
    asm volatile(
        "{\n\t.reg .pred p;\n\t"
        "setp.ne.u32 p, %5, 0;\n\t"
        "tcgen05.mma.cta_group::1.kind::tf32 [%0], %1, %2, %3, {%4, %4, %4, %4}, p;\n\t}"
        :: "r"(d_tmem), "l"(a_desc), "l"(b_desc), "r"(idesc), "r"(z), "r"(en)
        : "memory");
}

__device__ __forceinline__ void mbar_init(uint32_t mbar, uint32_t cnt) {
    asm volatile("mbarrier.init.shared.b64 [%0], %1;" :: "r"(mbar), "r"(cnt) : "memory");
}

__device__ __forceinline__ void mbar_wait(uint32_t mbar, uint32_t parity) {
    asm volatile(
        "{\n\t.reg .pred P;\n\t"
        "WL_%=:\n\t"
        "mbarrier.try_wait.parity.acquire.cta.shared::cta.b64 P, [%0], %1, 0x989680;\n\t"
        "@P bra.uni WD_%=;\n\t"
        "bra.uni WL_%=;\n\t"
        "WD_%=:\n\t}"
        :: "r"(mbar), "r"(parity) : "memory");
}

#define TC_ALLOC(dst_smem, n) \
    asm volatile("tcgen05.alloc.cta_group::1.sync.aligned.shared::cta.b32 [%0], %1;" \
                 :: "r"(dst_smem), "r"((uint32_t)(n)) : "memory")
#define TC_RELINQ() \
    asm volatile("tcgen05.relinquish_alloc_permit.cta_group::1.sync.aligned;")
#define TC_DEALLOC(tm, n) \
    asm volatile("tcgen05.dealloc.cta_group::1.sync.aligned.b32 %0, %1;" :: "r"(tm), "r"((uint32_t)(n)))
#define TC_COMMIT(mbar) \
    asm volatile("tcgen05.commit.cta_group::1.mbarrier::arrive::one.shared::cluster.b64 [%0];" \
                 :: "r"(mbar) : "memory")
#define TC_FENCE_AFTER()  asm volatile("tcgen05.fence::after_thread_sync;" ::: "memory")
#define TC_FENCE_BEFORE() asm volatile("tcgen05.fence::before_thread_sync;" ::: "memory")
#define FENCE_ASYNC() asm volatile("fence.proxy.async.shared::cta;" ::: "memory")
#define TC_WAIT_LD()  asm volatile("tcgen05.wait::ld.sync.aligned;" ::: "memory")

#define TC_LD_X32(r, addr) \
    asm volatile( \
        "tcgen05.ld.sync.aligned.32x32b.x32.b32 " \
        "{%0, %1, %2, %3, %4, %5, %6, %7, " \
        " %8, %9, %10, %11, %12, %13, %14, %15, " \
        " %16, %17, %18, %19, %20, %21, %22, %23, " \
        " %24, %25, %26, %27, %28, %29, %30, %31}, [%32];" \
        : "=r"((r)[0]),  "=r"((r)[1]),  "=r"((r)[2]),  "=r"((r)[3]), \
          "=r"((r)[4]),  "=r"((r)[5]),  "=r"((r)[6]),  "=r"((r)[7]), \
          "=r"((r)[8]),  "=r"((r)[9]),  "=r"((r)[10]), "=r"((r)[11]), \
          "=r"((r)[12]), "=r"((r)[13]), "=r"((r)[14]), "=r"((r)[15]), \
          "=r"((r)[16]), "=r"((r)[17]), "=r"((r)[18]), "=r"((r)[19]), \
          "=r"((r)[20]), "=r"((r)[21]), "=r"((r)[22]), "=r"((r)[23]), \
          "=r"((r)[24]), "=r"((r)[25]), "=r"((r)[26]), "=r"((r)[27]), \
          "=r"((r)[28]), "=r"((r)[29]), "=r"((r)[30]), "=r"((r)[31]) \
        : "r"(addr))
#endif  // HAS_TC

extern __shared__ char g_dyn_smem[];

__global__ __launch_bounds__(256, 1)
void gemm_kernel(const float* __restrict__ A,   // [T, D]
                 const float* __restrict__ W,   // [E, D]
                 float* __restrict__ C,         // [T, E]
                 int D, int E) {
#if HAS_TC
    // ======================= tcgen05 tf32 3x-emulation path ==================
    __shared__ uint32_t s_tmem;
    __shared__ __align__(16) unsigned long long s_mbar[2];

    const int tid  = threadIdx.x;
    const int wid  = tid >> 5;
    const int lane = tid & 31;

    // 1024-align the dynamic smem tile region
    uint32_t raw_u32  = smem_u32(g_dyn_smem);
    uint32_t tile_u32 = (raw_u32 + 1023u) & ~1023u;
    char*    tile_gen = g_dyn_smem + (tile_u32 - raw_u32);

    const uint32_t mbar_u32 = smem_u32(&s_mbar[0]);

    if (wid == 0) TC_ALLOC(smem_u32(&s_tmem), TMEM_NCOLS);
    if (tid == 0) { mbar_init(mbar_u32, 1); mbar_init(mbar_u32 + 8, 1); }
    __syncthreads();
    const uint32_t tmem = s_tmem;

    const int blockRow = blockIdx.y * BM;
    const int blockCol = blockIdx.x * BN;

    // producer mapping: thread covers 4 rows (p*32 + rb), one float4 column c4
    const int rb = (wid << 2) + (lane >> 3);   // 0..31
    const int c4 = lane & 7;                   // 0..7

    const float* aBase = A + (size_t)(blockRow + rb) * D + c4 * 4;
    const float* bBase = W + (size_t)(blockCol + rb) * D + c4 * 4;
    const size_t rstep = (size_t)32 * D;

    const int niter = D / BKF;
    int ph0 = 0, ph1 = 0;

    float4 bufA[4], bufB[4];
    #pragma unroll
    for (int p = 0; p < 4; p++) {
        bufA[p] = *(const float4*)(aBase + p * rstep);
        bufB[p] = *(const float4*)(bBase + p * rstep);
    }

    uint32_t en = 0;  // first MMA: enable_d = 0

    for (int i = 0; i < niter; i++) {
        const int s = i & 1;
        const uint32_t stage = (uint32_t)s * STAGE_BYTES;

        if (i >= 2) {
            if (s == 0) { mbar_wait(mbar_u32, ph0); ph0 ^= 1; }
            else        { mbar_wait(mbar_u32 + 8, ph1); ph1 ^= 1; }
        }

        // convert + swizzled STS
        #pragma unroll
        for (int p = 0; p < 4; p++) {
            const int row = rb + p * 32;
            const uint32_t off = SWZ128((uint32_t)(row * 128 + c4 * 16));
            float4 va = bufA[p], vb = bufB[p];
            float4 ah, al, bh, bl;
            ah.x = f2tf32(va.x); al.x = f2tf32(va.x - ah.x);
            ah.y = f2tf32(va.y); al.y = f2tf32(va.y - ah.y);
            ah.z = f2tf32(va.z); al.z = f2tf32(va.z - ah.z);
            ah.w = f2tf32(va.w); al.w = f2tf32(va.w - ah.w);
            bh.x = f2tf32(vb.x); bl.x = f2tf32(vb.x - bh.x);
            bh.y = f2tf32(vb.y); bl.y = f2tf32(vb.y - bh.y);
            bh.z = f2tf32(vb.z); bl.z = f2tf32(vb.z - bh.z);
            bh.w = f2tf32(vb.w); bl.w = f2tf32(vb.w - bh.w);
            *(float4*)(tile_gen + stage + A_HI_OFF + off) = ah;
            *(float4*)(tile_gen + stage + A_LO_OFF + off) = al;
            *(float4*)(tile_gen + stage + B_HI_OFF + off) = bh;
            *(float4*)(tile_gen + stage + B_LO_OFF + off) = bl;
        }

        // prefetch next chunk
        if (i + 1 < niter) {
            const int kt = (i + 1) * BKF;
            #pragma unroll
            for (int p = 0; p < 4; p++) {
                bufA[p] = *(const float4*)(aBase + p * rstep + kt);
                bufB[p] = *(const float4*)(bBase + p * rstep + kt);
            }
        }

        __syncthreads();

        if (tid == 0) {
            FENCE_ASYNC();
            const uint32_t sb = tile_u32 + stage;
            const uint64_t dah = mk_desc(sb + A_HI_OFF);
            const uint64_t dal = mk_desc(sb + A_LO_OFF);
            const uint64_t dbh = mk_desc(sb + B_HI_OFF);
            const uint64_t dbl = mk_desc(sb + B_LO_OFF);
            #pragma unroll
            for (int ks = 0; ks < 4; ks++) {
                const uint64_t o = 2 * ks;   // 8 tf32 = 32 bytes = 2x16B
                mma_tf32_ss(tmem, dah + o, dbh + o, IDESC, en); en = 1;
                mma_tf32_ss(tmem, dah + o, dbl + o, IDESC, 1);
                mma_tf32_ss(tmem, dal + o, dbh + o, IDESC, 1);
            }
            TC_COMMIT(mbar_u32 + (uint32_t)s * 8);
        }
    }

    // drain: one outstanding commit per stage
    mbar_wait(mbar_u32, ph0);
    mbar_wait(mbar_u32 + 8, ph1);
    TC_FENCE_AFTER();

    // epilogue: warps 0-3 read 128x128 fp32 from TMEM, 32 cols at a time
    if (wid < 4) {
        const int m = blockRow + wid * 32 + lane;
        #pragma unroll
        for (int cb = 0; cb < 128; cb += 32) {
            uint32_t r[32];
            TC_LD_X32(r, tmem + cb);
            TC_WAIT_LD();
            float* cr = C + (size_t)m * E + blockCol + cb;
            #pragma unroll
            for (int q = 0; q < 8; q++) {
                float4 v = make_float4(__uint_as_float(r[q * 4 + 0]),
                                       __uint_as_float(r[q * 4 + 1]),
                                       __uint_as_float(r[q * 4 + 2]),
                                       __uint_as_float(r[q * 4 + 3]));
                *(float4*)(cr + q * 4) = v;
            }
        }
        TC_FENCE_BEFORE();
    }
    __syncthreads();
    if (wid == 0) {
        TC_RELINQ();
        TC_DEALLOC(tmem, TMEM_NCOLS);
    }
#else
    // ======================= SIMT fp32 fallback (R1) ==========================
    __shared__ float As[BKF][BM];
    __shared__ float Bs[BKF][BN];

    const int tid = threadIdx.x;
    const int tx  = tid % 16;
    const int ty  = tid / 16;

    const int blockRow = blockIdx.y * BM;
    const int blockCol = blockIdx.x * BN;

    const float* Ab = A + (size_t)blockRow * D;
    const float* Bb = W + (size_t)blockCol * D;

    float acc[8][8];
    #pragma unroll
    for (int i = 0; i < 8; i++)
        #pragma unroll
        for (int j = 0; j < 8; j++) acc[i][j] = 0.0f;

    const int lr = tid / 8;
    const int lc = tid % 8;

    for (int kt = 0; kt < D; kt += BKF) {
        #pragma unroll
        for (int i = 0; i < 4; i++) {
            const int row = lr + i * 32;
            float4 va = *(const float4*)(Ab + (size_t)row * D + kt + lc * 4);
            As[lc * 4 + 0][row] = va.x;
            As[lc * 4 + 1][row] = va.y;
            As[lc * 4 + 2][row] = va.z;
            As[lc * 4 + 3][row] = va.w;
            float4 vb = *(const float4*)(Bb + (size_t)row * D + kt + lc * 4);
            Bs[lc * 4 + 0][row] = vb.x;
            Bs[lc * 4 + 1][row] = vb.y;
            Bs[lc * 4 + 2][row] = vb.z;
            Bs[lc * 4 + 3][row] = vb.w;
        }
        __syncthreads();

        #pragma unroll
        for (int k = 0; k < BKF; k++) {
            float a[8], b[8];
            *(float4*)&a[0] = *(const float4*)&As[k][ty * 8];
            *(float4*)&a[4] = *(const float4*)&As[k][ty * 8 + 4];
            *(float4*)&b[0] = *(const float4*)&Bs[k][tx * 8];
            *(float4*)&b[4] = *(const float4*)&Bs[k][tx * 8 + 4];
            #pragma unroll
            for (int i = 0; i < 8; i++)
                #pragma unroll
                for (int j = 0; j < 8; j++)
                    acc[i][j] = fmaf(a[i], b[j], acc[i][j]);
        }
        __syncthreads();
    }

    #pragma unroll
    for (int i = 0; i < 8; i++) {
        const int row = blockRow + ty * 8 + i;
        float* Cr = C + (size_t)row * E + blockCol + tx * 8;
        *(float4*)(Cr + 0) = make_float4(acc[i][0], acc[i][1], acc[i][2], acc[i][3]);
        *(float4*)(Cr + 4) = make_float4(acc[i][4], acc[i][5], acc[i][6], acc[i][7]);
    }
#endif
}

// ---------------------------------------------------------------------------
// Router: warp per token. Lane owns 8 experts in registers.
// ---------------------------------------------------------------------------
__global__ __launch_bounds__(256)
void router_topk_kernel(const float* __restrict__ C,     // [T, 256]
                        const float* __restrict__ bias,  // [256]
                        float* __restrict__ wout,        // [T, 8]
                        float* __restrict__ iout) {      // [T, 8]
    const int t    = blockIdx.x * 8 + (threadIdx.x >> 5);
    const int lane = threadIdx.x & 31;

    const float4* row = (const float4*)(C + (size_t)t * 256) + lane * 2;
    float4 v0 = row[0], v1 = row[1];
    const float4* bp = (const float4*)bias + lane * 2;
    float4 b0 = __ldg(bp), b1 = __ldg(bp + 1);

    float s[8] = {v0.x, v0.y, v0.z, v0.w, v1.x, v1.y, v1.z, v1.w};
    float bl[8] = {b0.x, b0.y, b0.z, b0.w, b1.x, b1.y, b1.z, b1.w};

    // max
    float m = s[0];
    #pragma unroll
    for (int j = 1; j < 8; j++) m = fmaxf(m, s[j]);
    #pragma unroll
    for (int off = 16; off > 0; off >>= 1)
        m = fmaxf(m, __shfl_xor_sync(0xffffffffu, m, off));

    // exp + sum
    float e[8];
    float su = 0.0f;
    #pragma unroll
    for (int j = 0; j < 8; j++) { e[j] = __expf(s[j] - m); su += e[j]; }
    #pragma unroll
    for (int off = 16; off > 0; off >>= 1)
        su += __shfl_xor_sync(0xffffffffu, su, off);
    const float inv = 1.0f / su;

    float prob[8], choice[8];
    #pragma unroll
    for (int j = 0; j < 8; j++) {
        prob[j]   = e[j] * inv;
        choice[j] = prob[j] + bl[j];
    }

    #pragma unroll
    for (int k = 0; k < TOP_K; k++) {
        float v = choice[0];
        int   li = 0;
        #pragma unroll
        for (int j = 1; j < 8; j++)
            if (choice[j] > v) { v = choice[j]; li = j; }
        int idx = lane * 8 + li;

        #pragma unroll
        for (int off = 16; off > 0; off >>= 1) {
            float ov = __shfl_xor_sync(0xffffffffu, v, off);
            int   oi = __shfl_xor_sync(0xffffffffu, idx, off);
            if (ov > v || (ov == v && oi < idx)) { v = ov; idx = oi; }
        }

        if (lane == (idx >> 3)) {
            const int jj = idx & 7;
            float pw = 0.0f;
            #pragma unroll
            for (int j = 0; j < 8; j++)
                if (j == jj) { pw = prob[j]; choice[j] = -INFINITY; }
            wout[(size_t)t * TOP_K + k] = pw * ROUTED_SCALE;
            iout[(size_t)t * TOP_K + k] = (float)idx;
        }
    }
}

// ----------------------------- launch ---------------------------------------
extern "C" void kernel_launch(void* const* d_in, const int* in_sizes, int n_in,
                              void* d_out, int out_size) {
    const float* H    = (const float*)d_in[0];  // [T, D]
    const float* W    = (const float*)d_in[1];  // [E, D]
    const float* bias = (const float*)d_in[2];  // [E]

    const int E = in_sizes[2];                  // 256
    const int D = in_sizes[1] / E;              // 4096
    const int T = in_sizes[0] / D;              // 16384

    float* out  = (float*)d_out;
    float* C    = out;                          // [T, E]
    float* wout = out + (size_t)T * E;          // [T, 8]
    float* iout = wout + (size_t)T * TOP_K;     // [T, 8]

    static int attr_set = 0;
    if (!attr_set) {
        cudaFuncSetAttribute(gemm_kernel,
                             cudaFuncAttributeMaxDynamicSharedMemorySize, DYN_SMEM);
        attr_set = 1;
    }

    dim3 grid(E / BN, T / BM);
    gemm_kernel<<<grid, 256, DYN_SMEM>>>(H, W, C, D, E);
    router_topk_kernel<<<T / 8, 256>>>(C, bias, wout, iout);
}

// round 4
// speedup vs baseline: 7.5836x; 1.6565x over previous
#include <cuda_runtime.h>
#include <math.h>
#include <stdint.h>

// LongcatFlashTopkRouter: T=16384, D=4096, E=256
#define TOP_K 8
#define ROUTED_SCALE 1.5f

#if defined(__CUDA_ARCH__) && \
    (defined(__CUDA_ARCH_FEAT_SM103_ALL) || defined(__CUDA_ARCH_FEAT_SM100_ALL) || \
     defined(__CUDA_ARCH_FEAT_SM101_ALL))
#define HAS_TC 1
#else
#define HAS_TC 0
#endif

// ---------------------------------------------------------------------------
// GEMM: C[t,e] = dot(H[t,:], W[e,:])  via bf16x3 emulation on tcgen05
// Tile: BM=128 x BN=256 (=E, one wave of 128 CTAs) x BK=32 floats
// SMEM stage: A_hi/A_lo [128x32 bf16, 8KB ea] + B_hi/B_lo [256x32 bf16, 16KB ea]
// ---------------------------------------------------------------------------
#define BM 128
#define BN 256
#define BKF 32
#define STAGE_BYTES 49152
#define A_HI_OFF 0
#define A_LO_OFF 8192
#define B_HI_OFF 16384
#define B_LO_OFF 32768
#define NSTAGE 3
#define DYN_SMEM (NSTAGE * STAGE_BYTES + 1024)

// idesc kind::f16 bf16: F32(1)<<4 | BF16(1)<<7 | BF16(1)<<10 | (N=128/8)<<17 | (M=128/16)<<24
#define IDESC 0x8200490u
#define TMEM_NCOLS 256

#if HAS_TC
__device__ __forceinline__ uint32_t smem_u32(const void* p) {
    uint32_t a;
    asm("{ .reg .u64 t; cvta.to.shared.u64 t, %1; cvt.u32.u64 %0, t; }" : "=r"(a) : "l"(p));
    return a;
}

// d = { upper = bf16(hi), lower = bf16(lo) }
__device__ __forceinline__ uint32_t pack_bf16x2(float hi, float lo) {
    uint32_t d;
    asm("cvt.rn.bf16x2.f32 %0, %1, %2;" : "=r"(d) : "f"(hi), "f"(lo));
    return d;
}

#define SWZ64(o) ((o) ^ (((o) >> 3) & 0x30))

// SW64 K-major descriptor: layout=4, version=1, SBO=32 (512B/8rows), LBO=1
__device__ __forceinline__ uint64_t mk_desc64(uint32_t addr) {
    const uint64_t base =
        (uint64_t(4) << 61) | (uint64_t(1) << 46) | (uint64_t(32) << 32) | (uint64_t(1) << 16);
    return base | ((uint64_t)(addr >> 4) & 0x3FFF);
}

__device__ __forceinline__ void mma_bf16_ss(uint32_t d_tmem, uint64_t a_desc, uint64_t b_desc,
                                            uint32_t en) {
    uint32_t z = 0;
    asm volatile(
        "{\n\t.reg .pred p;\n\t"
        "setp.ne.u32 p, %5, 0;\n\t"
        "tcgen05.mma.cta_group::1.kind::f16 [%0], %1, %2, %3, {%4, %4, %4, %4}, p;\n\t}"
        :: "r"(d_tmem), "l"(a_desc), "l"(b_desc), "r"(IDESC), "r"(z), "r"(en)
        : "memory");
}

__device__ __forceinline__ void mbar_init(uint32_t mbar, uint32_t cnt) {
    asm volatile("mbarrier.init.shared.b64 [%0], %1;" :: "r"(mbar), "r"(cnt) : "memory");
}

__device__ __forceinline__ void mbar_wait(uint32_t mbar, uint32_t parity) {
    asm volatile(
        "{\n\t.reg .pred P;\n\t"
        "WL_%=:\n\t"
        "mbarrier.try_wait.parity.acquire.cta.shared::cta.b64 P, [%0], %1, 0x989680;\n\t"
        "@P bra.uni WD_%=;\n\t"
        "bra.uni WL_%=;\n\t"
        "WD_%=:\n\t}"
        :: "r"(mbar), "r"(parity) : "memory");
}

#define TC_ALLOC(dst_smem, n) \
    asm volatile("tcgen05.alloc.cta_group::1.sync.aligned.shared::cta.b32 [%0], %1;" \
                 :: "r"(dst_smem), "r"((uint32_t)(n)) : "memory")
#define TC_RELINQ() \
    asm volatile("tcgen05.relinquish_alloc_permit.cta_group::1.sync.aligned;")
#define TC_DEALLOC(tm, n) \
    asm volatile("tcgen05.dealloc.cta_group::1.sync.aligned.b32 %0, %1;" :: "r"(tm), "r"((uint32_t)(n)))
#define TC_COMMIT(mbar) \
    asm volatile("tcgen05.commit.cta_group::1.mbarrier::arrive::one.shared::cluster.b64 [%0];" \
                 :: "r"(mbar) : "memory")
#define TC_FENCE_AFTER()  asm volatile("tcgen05.fence::after_thread_sync;" ::: "memory")
#define TC_FENCE_BEFORE() asm volatile("tcgen05.fence::before_thread_sync;" ::: "memory")
#define FENCE_ASYNC() asm volatile("fence.proxy.async.shared::cta;" ::: "memory")
#define TC_WAIT_LD()  asm volatile("tcgen05.wait::ld.sync.aligned;" ::: "memory")

#define TC_LD_X32(r, addr) \
    asm volatile( \
        "tcgen05.ld.sync.aligned.32x32b.x32.b32 " \
        "{%0, %1, %2, %3, %4, %5, %6, %7, " \
        " %8, %9, %10, %11, %12, %13, %14, %15, " \
        " %16, %17, %18, %19, %20, %21, %22, %23, " \
        " %24, %25, %26, %27, %28, %29, %30, %31}, [%32];" \
        : "=r"((r)[0]),  "=r"((r)[1]),  "=r"((r)[2]),  "=r"((r)[3]), \
          "=r"((r)[4]),  "=r"((r)[5]),  "=r"((r)[6]),  "=r"((r)[7]), \
          "=r"((r)[8]),  "=r"((r)[9]),  "=r"((r)[10]), "=r"((r)[11]), \
          "=r"((r)[12]), "=r"((r)[13]), "=r"((r)[14]), "=r"((r)[15]), \
          "=r"((r)[16]), "=r"((r)[17]), "=r"((r)[18]), "=r"((r)[19]), \
          "=r"((r)[20]), "=r"((r)[21]), "=r"((r)[22]), "=r"((r)[23]), \
          "=r"((r)[24]), "=r"((r)[25]), "=r"((r)[26]), "=r"((r)[27]), \
          "=r"((r)[28]), "=r"((r)[29]), "=r"((r)[30]), "=r"((r)[31]) \
        : "r"(addr))
#endif  // HAS_TC

extern __shared__ char g_dyn_smem[];

__global__ __launch_bounds__(256, 1)
void gemm_kernel(const float* __restrict__ A,   // [T, D]
                 const float* __restrict__ W,   // [E, D]
                 float* __restrict__ C,         // [T, E]
                 int D, int E) {
#if HAS_TC
    // ==================== tcgen05 bf16x3 emulation path =====================
    __shared__ uint32_t s_tmem;
    __shared__ __align__(16) unsigned long long s_mbar[NSTAGE];

    const int tid  = threadIdx.x;
    const int wid  = tid >> 5;
    const int lane = tid & 31;

    uint32_t raw_u32  = smem_u32(g_dyn_smem);
    uint32_t tile_u32 = (raw_u32 + 1023u) & ~1023u;
    char*    tile_gen = g_dyn_smem + (tile_u32 - raw_u32);

    const uint32_t mbar_u32 = smem_u32(&s_mbar[0]);

    if (wid == 0) TC_ALLOC(smem_u32(&s_tmem), TMEM_NCOLS);
    if (tid == 0) {
        mbar_init(mbar_u32, 1);
        mbar_init(mbar_u32 + 8, 1);
        mbar_init(mbar_u32 + 16, 1);
    }
    __syncthreads();
    const uint32_t tmem = s_tmem;

    const int blockRow = blockIdx.x * BM;

    // producer mapping: group g = tid>>3 (0..31), f4 column tid&7 (0..7)
    const int grp = tid >> 3;
    const int c4  = tid & 7;

    // A: 4 rounds, row = q*32 + grp ; B: 8 rounds, row = p*32 + grp
    const float* aBase = A + (size_t)(blockRow + grp) * D + c4 * 4;
    const float* bBase = W + (size_t)grp * D + c4 * 4;
    const size_t rstep = (size_t)32 * D;

    const int niter = D / BKF;   // 128
    int ph0 = 0, ph1 = 0, ph2 = 0;
    int s = 0;

    float4 bufA[4], bufB[8];
    #pragma unroll
    for (int q = 0; q < 4; q++) bufA[q] = *(const float4*)(aBase + q * rstep);
    #pragma unroll
    for (int p = 0; p < 8; p++) bufB[p] = *(const float4*)(bBase + p * rstep);

    const uint32_t rowOff  = (uint32_t)(grp * 64 + c4 * 8);   // byte offset base (row grp)
    uint32_t en = 0;

    for (int i = 0; i < niter; i++) {
        const uint32_t stage = (uint32_t)s * STAGE_BYTES;

        if (i >= NSTAGE) {
            if      (s == 0) { mbar_wait(mbar_u32,      ph0); ph0 ^= 1; }
            else if (s == 1) { mbar_wait(mbar_u32 + 8,  ph1); ph1 ^= 1; }
            else             { mbar_wait(mbar_u32 + 16, ph2); ph2 ^= 1; }
        }

        // ---- convert fp32 -> (hi, lo) bf16, swizzled STS ----
        #pragma unroll
        for (int q = 0; q < 4; q++) {
            const uint32_t off = SWZ64(rowOff + (uint32_t)q * 2048);  // 32 rows * 64B
            float4 f = bufA[q];
            uint32_t h0 = pack_bf16x2(f.y, f.x);
            uint32_t h1 = pack_bf16x2(f.w, f.z);
            float a0 = __uint_as_float(h0 << 16);
            float a1 = __uint_as_float(h0 & 0xFFFF0000u);
            float a2 = __uint_as_float(h1 << 16);
            float a3 = __uint_as_float(h1 & 0xFFFF0000u);
            uint32_t l0 = pack_bf16x2(f.y - a1, f.x - a0);
            uint32_t l1 = pack_bf16x2(f.w - a3, f.z - a2);
            *(uint2*)(tile_gen + stage + A_HI_OFF + off) = make_uint2(h0, h1);
            *(uint2*)(tile_gen + stage + A_LO_OFF + off) = make_uint2(l0, l1);
        }
        #pragma unroll
        for (int p = 0; p < 8; p++) {
            const uint32_t off = SWZ64(rowOff + (uint32_t)p * 2048);
            float4 f = bufB[p];
            uint32_t h0 = pack_bf16x2(f.y, f.x);
            uint32_t h1 = pack_bf16x2(f.w, f.z);
            float a0 = __uint_as_float(h0 << 16);
            float a1 = __uint_as_float(h0 & 0xFFFF0000u);
            float a2 = __uint_as_float(h1 << 16);
            float a3 = __uint_as_float(h1 & 0xFFFF0000u);
            uint32_t l0 = pack_bf16x2(f.y - a1, f.x - a0);
            uint32_t l1 = pack_bf16x2(f.w - a3, f.z - a2);
            *(uint2*)(tile_gen + stage + B_HI_OFF + off) = make_uint2(h0, h1);
            *(uint2*)(tile_gen + stage + B_LO_OFF + off) = make_uint2(l0, l1);
        }

        // ---- prefetch next K-chunk ----
        if (i + 1 < niter) {
            const int kt = (i + 1) * BKF;
            #pragma unroll
            for (int q = 0; q < 4; q++) bufA[q] = *(const float4*)(aBase + q * rstep + kt);
            #pragma unroll
            for (int p = 0; p < 8; p++) bufB[p] = *(const float4*)(bBase + p * rstep + kt);
        }

        __syncthreads();

        if (tid == 0) {
            FENCE_ASYNC();
            const uint32_t sb = tile_u32 + stage;
            const uint64_t dAh = mk_desc64(sb + A_HI_OFF);
            const uint64_t dAl = mk_desc64(sb + A_LO_OFF);
            const uint64_t dBh = mk_desc64(sb + B_HI_OFF);
            const uint64_t dBl = mk_desc64(sb + B_LO_OFF);
            // B upper half (rows 128..255): +8192 bytes = +512 desc units
            #pragma unroll
            for (int ks = 0; ks < 2; ks++) {
                const uint64_t o = 2 * ks;          // 16 bf16 = 32B = 2 units
                mma_bf16_ss(tmem,       dAh + o, dBh + o,       en);
                mma_bf16_ss(tmem + 128, dAh + o, dBh + 512 + o, en);
                en = 1;
                mma_bf16_ss(tmem,       dAh + o, dBl + o,       1);
                mma_bf16_ss(tmem + 128, dAh + o, dBl + 512 + o, 1);
                mma_bf16_ss(tmem,       dAl + o, dBh + o,       1);
                mma_bf16_ss(tmem + 128, dAl + o, dBh + 512 + o, 1);
            }
            if      (s == 0) TC_COMMIT(mbar_u32);
            else if (s == 1) TC_COMMIT(mbar_u32 + 8);
            else             TC_COMMIT(mbar_u32 + 16);
        }

        s = (s == NSTAGE - 1) ? 0 : s + 1;
    }

    // drain last commit of each stage
    mbar_wait(mbar_u32,      ph0);
    mbar_wait(mbar_u32 + 8,  ph1);
    mbar_wait(mbar_u32 + 16, ph2);
    TC_FENCE_AFTER();

    // epilogue: warps 0-3, lane = token row; read 256 fp32 cols
    if (wid < 4) {
        const int m = blockRow + wid * 32 + lane;
        #pragma unroll
        for (int cb = 0; cb < 256; cb += 32) {
            uint32_t r[32];
            TC_LD_X32(r, tmem + cb);
            TC_WAIT_LD();
            float* cr = C + (size_t)m * E + cb;
            #pragma unroll
            for (int q = 0; q < 8; q++) {
                *(float4*)(cr + q * 4) = make_float4(__uint_as_float(r[q * 4 + 0]),
                                                     __uint_as_float(r[q * 4 + 1]),
                                                     __uint_as_float(r[q * 4 + 2]),
                                                     __uint_as_float(r[q * 4 + 3]));
            }
        }
        TC_FENCE_BEFORE();
    }
    __syncthreads();
    if (wid == 0) {
        TC_RELINQ();
        TC_DEALLOC(tmem, TMEM_NCOLS);
    }
#else
    // ==================== SIMT fp32 fallback (BN=256 aware) ==================
    __shared__ float As[BKF][128];
    __shared__ float Bs[BKF][128];

    const int tid = threadIdx.x;
    const int tx  = tid % 16;
    const int ty  = tid / 16;

    const int blockRow = blockIdx.x * BM;

    for (int half = 0; half < 2; half++) {
        const int blockCol = half * 128;
        const float* Ab = A + (size_t)blockRow * D;
        const float* Bb = W + (size_t)blockCol * D;

        float acc[8][8];
        #pragma unroll
        for (int i = 0; i < 8; i++)
            #pragma unroll
            for (int j = 0; j < 8; j++) acc[i][j] = 0.0f;

        const int lr = tid / 8;
        const int lc = tid % 8;

        for (int kt = 0; kt < D; kt += BKF) {
            __syncthreads();
            #pragma unroll
            for (int i = 0; i < 4; i++) {
                const int row = lr + i * 32;
                float4 va = *(const float4*)(Ab + (size_t)row * D + kt + lc * 4);
                As[lc * 4 + 0][row] = va.x;
                As[lc * 4 + 1][row] = va.y;
                As[lc * 4 + 2][row] = va.z;
                As[lc * 4 + 3][row] = va.w;
                float4 vb = *(const float4*)(Bb + (size_t)row * D + kt + lc * 4);
                Bs[lc * 4 + 0][row] = vb.x;
                Bs[lc * 4 + 1][row] = vb.y;
                Bs[lc * 4 + 2][row] = vb.z;
                Bs[lc * 4 + 3][row] = vb.w;
            }
            __syncthreads();

            #pragma unroll
            for (int k = 0; k < BKF; k++) {
                float a[8], b[8];
                *(float4*)&a[0] = *(const float4*)&As[k][ty * 8];
                *(float4*)&a[4] = *(const float4*)&As[k][ty * 8 + 4];
                *(float4*)&b[0] = *(const float4*)&Bs[k][tx * 8];
                *(float4*)&b[4] = *(const float4*)&Bs[k][tx * 8 + 4];
                #pragma unroll
                for (int i = 0; i < 8; i++)
                    #pragma unroll
                    for (int j = 0; j < 8; j++)
                        acc[i][j] = fmaf(a[i], b[j], acc[i][j]);
            }
        }

        #pragma unroll
        for (int i = 0; i < 8; i++) {
            const int row = blockRow + ty * 8 + i;
            float* Cr = C + (size_t)row * E + blockCol + tx * 8;
            *(float4*)(Cr + 0) = make_float4(acc[i][0], acc[i][1], acc[i][2], acc[i][3]);
            *(float4*)(Cr + 4) = make_float4(acc[i][4], acc[i][5], acc[i][6], acc[i][7]);
        }
    }
#endif
}

// ---------------------------------------------------------------------------
// Router: warp per token; lane owns 8 experts. Value-max + ballot, cached
// per-lane local argmax (only winning lane recomputes).
// ---------------------------------------------------------------------------
__global__ __launch_bounds__(256)
void router_topk_kernel(const float* __restrict__ C,     // [T, 256]
                        const float* __restrict__ bias,  // [256]
                        float* __restrict__ wout,        // [T, 8]
                        float* __restrict__ iout) {      // [T, 8]
    const int t    = blockIdx.x * 8 + (threadIdx.x >> 5);
    const int lane = threadIdx.x & 31;

    const float4* row = (const float4*)(C + (size_t)t * 256) + lane * 2;
    float4 v0 = row[0], v1 = row[1];
    const float4* bp = (const float4*)bias + lane * 2;
    float4 b0 = __ldg(bp), b1 = __ldg(bp + 1);

    float sc[8] = {v0.x, v0.y, v0.z, v0.w, v1.x, v1.y, v1.z, v1.w};
    float bl[8] = {b0.x, b0.y, b0.z, b0.w, b1.x, b1.y, b1.z, b1.w};

    // softmax
    float m = sc[0];
    #pragma unroll
    for (int j = 1; j < 8; j++) m = fmaxf(m, sc[j]);
    #pragma unroll
    for (int off = 16; off > 0; off >>= 1)
        m = fmaxf(m, __shfl_xor_sync(0xffffffffu, m, off));

    float ex[8];
    float su = 0.0f;
    #pragma unroll
    for (int j = 0; j < 8; j++) { ex[j] = __expf(sc[j] - m); su += ex[j]; }
    #pragma unroll
    for (int off = 16; off > 0; off >>= 1)
        su += __shfl_xor_sync(0xffffffffu, su, off);
    const float inv = 1.0f / su;

    float prob[8], choice[8];
    #pragma unroll
    for (int j = 0; j < 8; j++) {
        prob[j]   = ex[j] * inv;
        choice[j] = prob[j] + bl[j];
    }

    // cached local argmax (lowest j on ties via strict >)
    float v = choice[0];
    int   li = 0;
    #pragma unroll
    for (int j = 1; j < 8; j++)
        if (choice[j] > v) { v = choice[j]; li = j; }

    #pragma unroll
    for (int k = 0; k < TOP_K; k++) {
        float g = v;
        #pragma unroll
        for (int off = 16; off > 0; off >>= 1)
            g = fmaxf(g, __shfl_xor_sync(0xffffffffu, g, off));
        // lowest lane holding the max -> lowest global index
        unsigned mask = __ballot_sync(0xffffffffu, v == g);
        int src = __ffs(mask) - 1;
        if (lane == src) {
            float pw = 0.0f;
            #pragma unroll
            for (int j = 0; j < 8; j++)
                if (j == li) { pw = prob[j]; choice[j] = -INFINITY; }
            wout[(size_t)t * TOP_K + k] = pw * ROUTED_SCALE;
            iout[(size_t)t * TOP_K + k] = (float)(lane * 8 + li);
            // recompute cached local max
            v = choice[0]; li = 0;
            #pragma unroll
            for (int j = 1; j < 8; j++)
                if (choice[j] > v) { v = choice[j]; li = j; }
        }
    }
}

// ----------------------------- launch ---------------------------------------
extern "C" void kernel_launch(void* const* d_in, const int* in_sizes, int n_in,
                              void* d_out, int out_size) {
    const float* H    = (const float*)d_in[0];  // [T, D]
    const float* W    = (const float*)d_in[1];  // [E, D]
    const float* bias = (const float*)d_in[2];  // [E]

    const int E = in_sizes[2];                  // 256
    const int D = in_sizes[1] / E;              // 4096
    const int T = in_sizes[0] / D;              // 16384

    float* out  = (float*)d_out;
    float* C    = out;                          // [T, E]
    float* wout = out + (size_t)T * E;          // [T, 8]
    float* iout = wout + (size_t)T * TOP_K;     // [T, 8]

    static int attr_set = 0;
    if (!attr_set) {
        cudaFuncSetAttribute(gemm_kernel,
                             cudaFuncAttributeMaxDynamicSharedMemorySize, DYN_SMEM);
        attr_set = 1;
    }

    gemm_kernel<<<T / BM, 256, DYN_SMEM>>>(H, W, C, D, E);
    router_topk_kernel<<<T / 8, 256>>>(C, bias, wout, iout);
}